// round 11
// baseline (speedup 1.0000x reference)
#include <cuda_runtime.h>
#include <math.h>

// ---------------------------------------------------------------------------
// ConvLSTM stack, R10: R9 (skewed pipeline + FFMA2) +
//   - L3/L4 merged to FT=4 gate groups (halved tile/value redundancy)
//   - contiguous-row thread mapping + hoisted value loads (vv reused over ky)
// 4x (ConvLSTM2D + MaxPool2x2) -> Dense(50) -> softmax.  B=32, T=24, fp32.
// ---------------------------------------------------------------------------

static constexpr int Bv = 32;
static constexpr int Tv = 24;

__device__ float g_hs1[(size_t)Bv*Tv*126*126*4];
__device__ float g_c1 [(size_t)Bv*126*126*4];
__device__ float g_p1 [(size_t)Bv*Tv*63*63*4];
__device__ float g_hs2[(size_t)Bv*Tv*61*61*8];
__device__ float g_c2 [(size_t)Bv*61*61*8];
__device__ float g_p2 [(size_t)Bv*Tv*31*31*8];
__device__ float g_hs3[(size_t)Bv*Tv*29*29*12];
__device__ float g_c3 [(size_t)Bv*29*29*12];
__device__ float g_p3 [(size_t)Bv*Tv*15*15*12];
__device__ float g_hs4[(size_t)Bv*Tv*13*13*16];
__device__ float g_c4 [(size_t)Bv*13*13*16];
__device__ float g_p4 [(size_t)Bv*Tv*7*7*16];
__device__ float g_logits[Bv*50];

__device__ __forceinline__ float hsig(float x) { return __saturatef(0.2f * x + 0.5f); }

__device__ __forceinline__ unsigned long long pack2(float v) {
    unsigned long long r;
    asm("mov.b64 %0, {%1, %1};" : "=l"(r) : "f"(v));
    return r;
}
__device__ __forceinline__ void ffma2(unsigned long long& d, unsigned long long a,
                                      unsigned long long b) {
    asm("fma.rn.f32x2 %0, %1, %2, %0;" : "+l"(d) : "l"(a), "l"(b));
}

static constexpr int SMEM_RAW = 38720;   // >= max per-layer need (38720 B, L3)

// One ConvLSTM timestep for one layer + fused 2x2 maxpool.
// Flat 256-thread block; FT gate channels per block (G4 = 4*FT gate values,
// NQ = G4/2 packed f32x2 accumulators). Threads cover PY CONTIGUOUS rows
// (ry = ly*PY + p) so one vv[PY+2] value array serves all 3 ky taps.
template<int CIN, int F, int FT, int HIN, int WIN, int TX, int TY>
__device__ __forceinline__ void lstm_impl(
    char* raw, int bid,
    const float* __restrict__ in_seq,   // (B,T,HIN,WIN,CIN)
    const float* __restrict__ Wx,       // (3,3,CIN,4F)
    const float* __restrict__ Wh,       // (3,3,F,4F)
    const float* __restrict__ bias,     // (4F,)
    float* __restrict__ hs,             // (B,T,HO,WO,F)
    float* __restrict__ c_buf,          // (B,HO,WO,F)
    float* __restrict__ pool_out,       // (B,T,HOp,WOp,F)
    int t)
{
    constexpr int NTHR = 256;
    constexpr int BY = NTHR / TX;
    constexpr int PY = (TY + BY - 1) / BY;
    constexpr int BYP = BY * PY;
    constexpr int G4 = 4 * FT;
    constexpr int NQ = G4 / 2;          // packed accumulators (8 or 4)
    constexpr int NH = NQ / 4;          // groups of 4 b64 weights (2 or 1)
    constexpr int HO = HIN - 2, WO = WIN - 2;
    constexpr int HOp = (HO + 1) / 2, WOp = (WO + 1) / 2;
    constexpr int C4 = 4 * F;
    constexpr int TXP = TX + 2, TYP = TY + 2;
    constexpr int NXT = (WO + TX - 1) / TX;
    constexpr int NYT = (HO + TY - 1) / TY;
    constexpr int NG = F / FT;

    float* s_in = reinterpret_cast<float*>(raw);
    float* s_h  = s_in + CIN * TYP * TXP;
    float* s_wx = s_h  + F * TYP * TXP;
    float* s_wh = s_wx + 9 * CIN * G4;
    float* s_pool = s_h;   // reused after mainloop

    int r = bid;
    const int g  = r % NG;  r /= NG;
    const int xT = r % NXT; r /= NXT;
    const int yT = r % NYT; const int b = r / NYT;
    const int x0 = xT * TX, y0 = yT * TY;     // even (or single tile)
    const int f0 = g * FT;
    const int tid = threadIdx.x;
    const int lx = tid % TX, ly = tid / TX;

    // ---- weights (gate-column slice) into smem: [(tap*C+ci)][g*FT+j] ----
    for (int i = tid; i < 9 * CIN * G4; i += NTHR) {
        int col = i % G4, rc = i / G4;
        s_wx[i] = Wx[rc * C4 + (col / FT) * F + f0 + (col % FT)];
    }
    for (int i = tid; i < 9 * F * G4; i += NTHR) {
        int col = i % G4, rc = i / G4;
        s_wh[i] = Wh[rc * C4 + (col / FT) * F + f0 + (col % FT)];
    }

    // ---- input tile (planar, zero-padded) ----
    {
        const float* xin = in_seq + ((size_t)(b * Tv + t)) * HIN * WIN * CIN;
        for (int i = tid; i < TYP * TXP * CIN; i += NTHR) {
            int ci = i % CIN; int rr = i / CIN;
            int xx = rr % TXP; int yy = rr / TXP;
            int gy = y0 + yy, gx = x0 + xx;
            float v = (gy < HIN && gx < WIN) ? __ldg(&xin[((size_t)gy * WIN + gx) * CIN + ci]) : 0.0f;
            s_in[(ci * TYP + yy) * TXP + xx] = v;
        }
    }
    // ---- h_{t-1} tile (planar, zero-padded) ----
    if (t > 0) {
        const float* hp = hs + ((size_t)(b * Tv + (t - 1))) * HO * WO * F;
        for (int i = tid; i < TYP * TXP * F; i += NTHR) {
            int ci = i % F; int rr = i / F;
            int xx = rr % TXP; int yy = rr / TXP;
            int hr = y0 - 1 + yy, hc = x0 - 1 + xx;
            float v = (hr >= 0 && hr < HO && hc >= 0 && hc < WO)
                        ? __ldg(&hp[((size_t)hr * WO + hc) * F + ci]) : 0.0f;
            s_h[(ci * TYP + yy) * TXP + xx] = v;
        }
    }
    __syncthreads();

    // Contiguous-row mapping: thread covers rows ry = ly*PY + p.
    int ry[PY];
    #pragma unroll
    for (int p = 0; p < PY; p++) ry[p] = ly * PY + p;
    // Base row for value loads, clamped so vv indices stay inside TYP.
    int vrow[PY + 2];
    #pragma unroll
    for (int u = 0; u < PY + 2; u++) {
        int rr = ly * PY + u;
        vrow[u] = (rr < TYP) ? rr : (TYP - 1);
    }

    // Packed accumulators: acc[p][q] = gate values (2q, 2q+1)
    unsigned long long acc[PY][NQ];
    {
        #pragma unroll
        for (int q = 0; q < NQ; q++) {
            int m0 = 2 * q, m1 = 2 * q + 1;
            float b0 = __ldg(&bias[(m0 / FT) * F + f0 + (m0 % FT)]);
            float b1 = __ldg(&bias[(m1 / FT) * F + f0 + (m1 % FT)]);
            unsigned long long bp;
            asm("mov.b64 %0, {%1, %2};" : "=l"(bp) : "f"(b0), "f"(b1));
            #pragma unroll
            for (int p = 0; p < PY; p++) acc[p][q] = bp;
        }
    }

    // ---- input conv (VALID); hoisted values reused across ky ----
    #pragma unroll
    for (int kx = 0; kx < 3; kx++) {
        #pragma unroll
        for (int ci = 0; ci < CIN; ci++) {
            unsigned long long vv[PY + 2];
            #pragma unroll
            for (int u = 0; u < PY + 2; u++)
                vv[u] = pack2(s_in[(ci * TYP + vrow[u]) * TXP + lx + kx]);
            #pragma unroll
            for (int h = 0; h < NH; h++) {
                #pragma unroll
                for (int ky = 0; ky < 3; ky++) {
                    const ulonglong2* wq = reinterpret_cast<const ulonglong2*>(
                        s_wx + ((ky * 3 + kx) * CIN + ci) * G4);
                    ulonglong2 a = wq[2 * h], c = wq[2 * h + 1];
                    #pragma unroll
                    for (int p = 0; p < PY; p++) {
                        ffma2(acc[p][4 * h + 0], vv[ky + p], a.x);
                        ffma2(acc[p][4 * h + 1], vv[ky + p], a.y);
                        ffma2(acc[p][4 * h + 2], vv[ky + p], c.x);
                        ffma2(acc[p][4 * h + 3], vv[ky + p], c.y);
                    }
                }
            }
        }
    }

    // ---- recurrent conv (SAME) ----
    if (t > 0) {
        #pragma unroll
        for (int kx = 0; kx < 3; kx++) {
            #pragma unroll
            for (int ci = 0; ci < F; ci++) {
                unsigned long long vv[PY + 2];
                #pragma unroll
                for (int u = 0; u < PY + 2; u++)
                    vv[u] = pack2(s_h[(ci * TYP + vrow[u]) * TXP + lx + kx]);
                #pragma unroll
                for (int h = 0; h < NH; h++) {
                    #pragma unroll
                    for (int ky = 0; ky < 3; ky++) {
                        const ulonglong2* wq = reinterpret_cast<const ulonglong2*>(
                            s_wh + ((ky * 3 + kx) * F + ci) * G4);
                        ulonglong2 a = wq[2 * h], c = wq[2 * h + 1];
                        #pragma unroll
                        for (int p = 0; p < PY; p++) {
                            ffma2(acc[p][4 * h + 0], vv[ky + p], a.x);
                            ffma2(acc[p][4 * h + 1], vv[ky + p], a.y);
                            ffma2(acc[p][4 * h + 2], vv[ky + p], c.x);
                            ffma2(acc[p][4 * h + 3], vv[ky + p], c.y);
                        }
                    }
                }
            }
        }
    }

    __syncthreads();   // all s_h reads done; safe to reuse as s_pool

    // ---- gates (i, f, c, o), write c/h, stage h for pooling ----
    #pragma unroll
    for (int p = 0; p < PY; p++) {
        int gy = y0 + ry[p];
        int gx = x0 + lx;
        bool valid = (ry[p] < TY) && (gy < HO) && (gx < WO);
        float hn[FT];
        #pragma unroll
        for (int j = 0; j < FT; j++) hn[j] = -INFINITY;

        if (valid) {
            float va[G4];
            #pragma unroll
            for (int q = 0; q < NQ; q++) {
                unsigned int lo, hi;
                asm("mov.b64 {%0, %1}, %2;" : "=r"(lo), "=r"(hi) : "l"(acc[p][q]));
                va[2 * q]     = __uint_as_float(lo);
                va[2 * q + 1] = __uint_as_float(hi);
            }
            size_t pix = (size_t)b * HO * WO + (size_t)gy * WO + gx;
            float* cp = c_buf + pix * F + f0;
            float* ho = hs + ((size_t)(b * Tv + t)) * HO * WO * F
                           + ((size_t)gy * WO + gx) * F + f0;
            float co[FT];
            if (t > 0) {
                if constexpr (FT == 4) {
                    float4 c4v = *reinterpret_cast<const float4*>(cp);
                    co[0] = c4v.x; co[1] = c4v.y; co[2] = c4v.z; co[3] = c4v.w;
                } else {
                    float2 c2v = *reinterpret_cast<const float2*>(cp);
                    co[0] = c2v.x; co[1] = c2v.y;
                }
            } else {
                #pragma unroll
                for (int j = 0; j < FT; j++) co[j] = 0.0f;
            }
            float cn[FT];
            #pragma unroll
            for (int j = 0; j < FT; j++) {
                float iv = va[j];
                float fv = va[FT + j];
                float cv = va[2 * FT + j];
                float ov = va[3 * FT + j];
                float c2 = hsig(fv) * co[j] + hsig(iv) * tanhf(cv);
                cn[j] = c2;
                hn[j] = hsig(ov) * tanhf(c2);
            }
            if constexpr (FT == 4) {
                *reinterpret_cast<float4*>(cp) = make_float4(cn[0], cn[1], cn[2], cn[3]);
                *reinterpret_cast<float4*>(ho) = make_float4(hn[0], hn[1], hn[2], hn[3]);
            } else {
                *reinterpret_cast<float2*>(cp) = make_float2(cn[0], cn[1]);
                *reinterpret_cast<float2*>(ho) = make_float2(hn[0], hn[1]);
            }
        }
        if (ry[p] < BYP) {
            #pragma unroll
            for (int j = 0; j < FT; j++)
                s_pool[(j * BYP + ry[p]) * TX + lx] = hn[j];   // -INF if invalid
        }
    }
    __syncthreads();

    // ---- fused 2x2 maxpool (SAME) on the staged tile ----
    {
        constexpr int TXH = TX / 2, TYH = (TY + 1) / 2;
        for (int i = tid; i < FT * TYH * TXH; i += NTHR) {
            int f = i % FT; int rr = i / FT;
            int oxc = rr % TXH, oyc = rr / TXH;
            int oy = (y0 >> 1) + oyc, ox = (x0 >> 1) + oxc;
            if (oy < HOp && ox < WOp) {
                int r0 = 2 * oyc, r1 = r0 + 1, q0 = 2 * oxc, q1 = q0 + 1;
                float m = fmaxf(s_pool[(f * BYP + r0) * TX + q0],
                                s_pool[(f * BYP + r0) * TX + q1]);
                if (r1 < TY)
                    m = fmaxf(m, fmaxf(s_pool[(f * BYP + r1) * TX + q0],
                                       s_pool[(f * BYP + r1) * TX + q1]));
                pool_out[(((size_t)(b * Tv + t) * HOp + oy) * WOp + ox) * F + f0 + f] = m;
            }
        }
    }
}

// Block counts per layer (flat grid, L1 first = longest first)
static constexpr int NB1 = 1024;   // 32b * 8yt * 4xt * 1g
static constexpr int NB2 = 512;    // 32b * 4yt * 2xt * 2g
static constexpr int NB3 = 384;    // 32b * 4yt * 1xt * 3g   (FT=4)
static constexpr int NB4 = 256;    // 32b * 2yt * 1xt * 4g   (FT=4, TY=8)
static constexpr int NBT = NB1 + NB2 + NB3 + NB4;   // 2176

// Mega-step: flat grid, block ranges select the layer; skewed timesteps.
__global__ void __launch_bounds__(256, 4) mega_step(
    const float* __restrict__ x,
    const float* __restrict__ Wx1, const float* __restrict__ Wh1, const float* __restrict__ b1,
    const float* __restrict__ Wx2, const float* __restrict__ Wh2, const float* __restrict__ b2,
    const float* __restrict__ Wx3, const float* __restrict__ Wh3, const float* __restrict__ b3,
    const float* __restrict__ Wx4, const float* __restrict__ Wh4, const float* __restrict__ b4,
    float* hs1, float* c1, float* p1,
    float* hs2, float* c2, float* p2,
    float* hs3, float* c3, float* p3,
    float* hs4, float* c4, float* p4,
    int t1, int t2, int t3, int t4)
{
    __shared__ __align__(16) char raw[SMEM_RAW];
    const int bid = blockIdx.x;
    if (bid < NB1) {
        if (t1 >= 0)
            lstm_impl<3, 4, 4, 128, 128, 32, 16>(raw, bid, x, Wx1, Wh1, b1, hs1, c1, p1, t1);
    } else if (bid < NB1 + NB2) {
        if (t2 >= 0)
            lstm_impl<4, 8, 4, 63, 63, 32, 16>(raw, bid - NB1, p1, Wx2, Wh2, b2, hs2, c2, p2, t2);
    } else if (bid < NB1 + NB2 + NB3) {
        if (t3 >= 0)
            lstm_impl<8, 12, 4, 31, 31, 32, 8>(raw, bid - NB1 - NB2, p2, Wx3, Wh3, b3, hs3, c3, p3, t3);
    } else {
        if (t4 >= 0)
            lstm_impl<12, 16, 4, 15, 15, 16, 8>(raw, bid - NB1 - NB2 - NB3, p3, Wx4, Wh4, b4, hs4, c4, p4, t4);
    }
}

// Dense: logits[b,k] = sum_j xf[b,j]*Wd[j,k] + bd[k];   FLAT=18816, NC=50
__global__ void dense_k(const float* __restrict__ xf, const float* __restrict__ Wd,
                        const float* __restrict__ bd, float* __restrict__ logits)
{
    const int FLAT = 18816, NC = 50;
    int b = blockIdx.x, k = blockIdx.y;
    float s = 0.0f;
    for (int j = threadIdx.x; j < FLAT; j += blockDim.x)
        s += xf[(size_t)b * FLAT + j] * __ldg(&Wd[(size_t)j * NC + k]);
    __shared__ float red[128];
    red[threadIdx.x] = s;
    __syncthreads();
    for (int off = 64; off > 0; off >>= 1) {
        if (threadIdx.x < off) red[threadIdx.x] += red[threadIdx.x + off];
        __syncthreads();
    }
    if (threadIdx.x == 0) logits[b * NC + k] = red[0] + __ldg(&bd[k]);
}

__global__ void softmax_k(const float* __restrict__ logits, float* __restrict__ out)
{
    const int NC = 50;
    int b = blockIdx.x, t = threadIdx.x;
    __shared__ float s[64];
    float v = (t < NC) ? logits[b * NC + t] : -INFINITY;
    s[t] = v; __syncthreads();
    for (int off = 32; off > 0; off >>= 1) {
        if (t < off) s[t] = fmaxf(s[t], s[t + off]);
        __syncthreads();
    }
    float m = s[0]; __syncthreads();
    float e = (t < NC) ? expf(v - m) : 0.0f;
    s[t] = e; __syncthreads();
    for (int off = 32; off > 0; off >>= 1) {
        if (t < off) s[t] += s[t + off];
        __syncthreads();
    }
    float sum = s[0];
    if (t < NC) out[b * NC + t] = e / sum;
}

template <typename Sym>
static float* symaddr(const Sym& s) {
    void* p = nullptr;
    cudaGetSymbolAddress(&p, s);
    return (float*)p;
}

extern "C" void kernel_launch(void* const* d_in, const int* in_sizes, int n_in,
                              void* d_out, int out_size)
{
    const float* x   = (const float*)d_in[0];
    const float* Wx1 = (const float*)d_in[1];
    const float* Wh1 = (const float*)d_in[2];
    const float* b1  = (const float*)d_in[3];
    const float* Wx2 = (const float*)d_in[4];
    const float* Wh2 = (const float*)d_in[5];
    const float* b2  = (const float*)d_in[6];
    const float* Wx3 = (const float*)d_in[7];
    const float* Wh3 = (const float*)d_in[8];
    const float* b3  = (const float*)d_in[9];
    const float* Wx4 = (const float*)d_in[10];
    const float* Wh4 = (const float*)d_in[11];
    const float* b4  = (const float*)d_in[12];
    const float* Wd  = (const float*)d_in[13];
    const float* bd  = (const float*)d_in[14];
    float* out = (float*)d_out;

    float* hs1 = symaddr(g_hs1); float* c1 = symaddr(g_c1); float* p1 = symaddr(g_p1);
    float* hs2 = symaddr(g_hs2); float* c2 = symaddr(g_c2); float* p2 = symaddr(g_p2);
    float* hs3 = symaddr(g_hs3); float* c3 = symaddr(g_c3); float* p3 = symaddr(g_p3);
    float* hs4 = symaddr(g_hs4); float* c4 = symaddr(g_c4); float* p4 = symaddr(g_p4);
    float* logits = symaddr(g_logits);

    // Skewed pipeline: launch s runs L1@s, L2@s-1, L3@s-2, L4@s-3.
    dim3 grid(NBT), blk(256);
    for (int s = 0; s < Tv + 3; s++) {
        int t1 = (s < Tv) ? s : -1;
        int t2 = (s - 1 >= 0 && s - 1 < Tv) ? s - 1 : -1;
        int t3 = (s - 2 >= 0 && s - 2 < Tv) ? s - 2 : -1;
        int t4 = (s - 3 >= 0 && s - 3 < Tv) ? s - 3 : -1;
        mega_step<<<grid, blk>>>(x,
                                 Wx1, Wh1, b1, Wx2, Wh2, b2,
                                 Wx3, Wh3, b3, Wx4, Wh4, b4,
                                 hs1, c1, p1, hs2, c2, p2,
                                 hs3, c3, p3, hs4, c4, p4,
                                 t1, t2, t3, t4);
    }

    // ---- Dense + softmax ----
    dim3 dgrid(Bv, 50);
    dense_k<<<dgrid, 128>>>(p4, Wd, bd, logits);
    softmax_k<<<Bv, 64>>>(logits, out);
}

// round 12
// speedup vs baseline: 1.0194x; 1.0194x over previous
#include <cuda_runtime.h>
#include <math.h>

// ---------------------------------------------------------------------------
// ConvLSTM stack, R11: exact R9 kernel (skewed pipeline + FFMA2, best known
// 2517us) with ONE change: __launch_bounds__(256,5) to lift occupancy
// 4 -> 5 blocks/SM (regs 64 -> <=48). smem 38.4KB permits 5 blocks.
// ---------------------------------------------------------------------------

static constexpr int Bv = 32;
static constexpr int Tv = 24;

__device__ float g_hs1[(size_t)Bv*Tv*126*126*4];
__device__ float g_c1 [(size_t)Bv*126*126*4];
__device__ float g_p1 [(size_t)Bv*Tv*63*63*4];
__device__ float g_hs2[(size_t)Bv*Tv*61*61*8];
__device__ float g_c2 [(size_t)Bv*61*61*8];
__device__ float g_p2 [(size_t)Bv*Tv*31*31*8];
__device__ float g_hs3[(size_t)Bv*Tv*29*29*12];
__device__ float g_c3 [(size_t)Bv*29*29*12];
__device__ float g_p3 [(size_t)Bv*Tv*15*15*12];
__device__ float g_hs4[(size_t)Bv*Tv*13*13*16];
__device__ float g_c4 [(size_t)Bv*13*13*16];
__device__ float g_p4 [(size_t)Bv*Tv*7*7*16];
__device__ float g_logits[Bv*50];

__device__ __forceinline__ float hsig(float x) { return __saturatef(0.2f * x + 0.5f); }

__device__ __forceinline__ unsigned long long pack2(float v) {
    unsigned long long r;
    asm("mov.b64 %0, {%1, %1};" : "=l"(r) : "f"(v));
    return r;
}
__device__ __forceinline__ void ffma2(unsigned long long& d, unsigned long long a,
                                      unsigned long long b) {
    asm("fma.rn.f32x2 %0, %1, %2, %0;" : "+l"(d) : "l"(a), "l"(b));
}

static constexpr int SMEM_RAW = 38400;   // >= max per-layer need (38304 B, L4)

// One ConvLSTM timestep for one layer + fused 2x2 maxpool.
// Flat 256-thread block; FT gate channels per block (G4 = 4*FT gate values,
// held as NQ = G4/2 packed f32x2 accumulators).
template<int CIN, int F, int FT, int HIN, int WIN, int TX, int TY>
__device__ __forceinline__ void lstm_impl(
    char* raw, int bid,
    const float* __restrict__ in_seq,   // (B,T,HIN,WIN,CIN)
    const float* __restrict__ Wx,       // (3,3,CIN,4F)
    const float* __restrict__ Wh,       // (3,3,F,4F)
    const float* __restrict__ bias,     // (4F,)
    float* __restrict__ hs,             // (B,T,HO,WO,F)
    float* __restrict__ c_buf,          // (B,HO,WO,F)
    float* __restrict__ pool_out,       // (B,T,HOp,WOp,F)
    int t)
{
    constexpr int NTHR = 256;
    constexpr int BY = NTHR / TX;
    constexpr int PY = (TY + BY - 1) / BY;
    constexpr int BYP = BY * PY;
    constexpr int G4 = 4 * FT;
    constexpr int NQ = G4 / 2;          // packed accumulators (8 or 4)
    constexpr int NH = NQ / 4;          // halves of 4 b64 (2 or 1)
    constexpr int HO = HIN - 2, WO = WIN - 2;
    constexpr int HOp = (HO + 1) / 2, WOp = (WO + 1) / 2;
    constexpr int C4 = 4 * F;
    constexpr int TXP = TX + 2, TYP = TY + 2;
    constexpr int NXT = (WO + TX - 1) / TX;
    constexpr int NYT = (HO + TY - 1) / TY;
    constexpr int NG = F / FT;

    float* s_in = reinterpret_cast<float*>(raw);
    float* s_h  = s_in + CIN * TYP * TXP;
    float* s_wx = s_h  + F * TYP * TXP;
    float* s_wh = s_wx + 9 * CIN * G4;
    float* s_pool = s_h;   // reused after mainloop

    int r = bid;
    const int g  = r % NG;  r /= NG;
    const int xT = r % NXT; r /= NXT;
    const int yT = r % NYT; const int b = r / NYT;
    const int x0 = xT * TX, y0 = yT * TY;     // even (or single tile)
    const int f0 = g * FT;
    const int tid = threadIdx.x;
    const int lx = tid % TX, ly = tid / TX;

    // ---- weights (gate-column slice) into smem: [(tap*C+ci)][g*FT+j] ----
    for (int i = tid; i < 9 * CIN * G4; i += NTHR) {
        int col = i % G4, rc = i / G4;
        s_wx[i] = Wx[rc * C4 + (col / FT) * F + f0 + (col % FT)];
    }
    for (int i = tid; i < 9 * F * G4; i += NTHR) {
        int col = i % G4, rc = i / G4;
        s_wh[i] = Wh[rc * C4 + (col / FT) * F + f0 + (col % FT)];
    }

    // ---- input tile (planar, zero-padded) ----
    {
        const float* xin = in_seq + ((size_t)(b * Tv + t)) * HIN * WIN * CIN;
        for (int i = tid; i < TYP * TXP * CIN; i += NTHR) {
            int ci = i % CIN; int rr = i / CIN;
            int xx = rr % TXP; int yy = rr / TXP;
            int gy = y0 + yy, gx = x0 + xx;
            float v = (gy < HIN && gx < WIN) ? __ldg(&xin[((size_t)gy * WIN + gx) * CIN + ci]) : 0.0f;
            s_in[(ci * TYP + yy) * TXP + xx] = v;
        }
    }
    // ---- h_{t-1} tile (planar, zero-padded) ----
    if (t > 0) {
        const float* hp = hs + ((size_t)(b * Tv + (t - 1))) * HO * WO * F;
        for (int i = tid; i < TYP * TXP * F; i += NTHR) {
            int ci = i % F; int rr = i / F;
            int xx = rr % TXP; int yy = rr / TXP;
            int hr = y0 - 1 + yy, hc = x0 - 1 + xx;
            float v = (hr >= 0 && hr < HO && hc >= 0 && hc < WO)
                        ? __ldg(&hp[((size_t)hr * WO + hc) * F + ci]) : 0.0f;
            s_h[(ci * TYP + yy) * TXP + xx] = v;
        }
    }
    __syncthreads();

    // Row indices per sub-pixel p: ry = logical row, rcl = clamped for smem reads.
    int ry[PY], rcl[PY];
    #pragma unroll
    for (int p = 0; p < PY; p++) {
        ry[p] = ly + p * BY;
        rcl[p] = (ry[p] < TY) ? ry[p] : (TY - 1);
    }

    // Packed accumulators: acc[p][q] = gate values (2q, 2q+1)
    unsigned long long acc[PY][NQ];
    {
        #pragma unroll
        for (int q = 0; q < NQ; q++) {
            int m0 = 2 * q, m1 = 2 * q + 1;
            float b0 = __ldg(&bias[(m0 / FT) * F + f0 + (m0 % FT)]);
            float b1 = __ldg(&bias[(m1 / FT) * F + f0 + (m1 % FT)]);
            unsigned long long bp;
            asm("mov.b64 %0, {%1, %2};" : "=l"(bp) : "f"(b0), "f"(b1));
            #pragma unroll
            for (int p = 0; p < PY; p++) acc[p][q] = bp;
        }
    }

    // ---- input conv (VALID); FFMA2, weight halves of 4 b64 ----
    #pragma unroll
    for (int ky = 0; ky < 3; ky++) {
        #pragma unroll
        for (int kx = 0; kx < 3; kx++) {
            #pragma unroll
            for (int ci = 0; ci < CIN; ci++) {
                unsigned long long vv[PY];
                #pragma unroll
                for (int p = 0; p < PY; p++)
                    vv[p] = pack2(s_in[(ci * TYP + rcl[p] + ky) * TXP + lx + kx]);
                const ulonglong2* wq = reinterpret_cast<const ulonglong2*>(
                    s_wx + ((ky * 3 + kx) * CIN + ci) * G4);
                #pragma unroll
                for (int h = 0; h < NH; h++) {
                    ulonglong2 a = wq[2 * h], c = wq[2 * h + 1];
                    #pragma unroll
                    for (int p = 0; p < PY; p++) {
                        ffma2(acc[p][4 * h + 0], vv[p], a.x);
                        ffma2(acc[p][4 * h + 1], vv[p], a.y);
                        ffma2(acc[p][4 * h + 2], vv[p], c.x);
                        ffma2(acc[p][4 * h + 3], vv[p], c.y);
                    }
                }
            }
        }
    }

    // ---- recurrent conv (SAME) ----
    if (t > 0) {
        #pragma unroll
        for (int ky = 0; ky < 3; ky++) {
            #pragma unroll
            for (int kx = 0; kx < 3; kx++) {
                #pragma unroll
                for (int ci = 0; ci < F; ci++) {
                    unsigned long long vv[PY];
                    #pragma unroll
                    for (int p = 0; p < PY; p++)
                        vv[p] = pack2(s_h[(ci * TYP + rcl[p] + ky) * TXP + lx + kx]);
                    const ulonglong2* wq = reinterpret_cast<const ulonglong2*>(
                        s_wh + ((ky * 3 + kx) * F + ci) * G4);
                    #pragma unroll
                    for (int h = 0; h < NH; h++) {
                        ulonglong2 a = wq[2 * h], c = wq[2 * h + 1];
                        #pragma unroll
                        for (int p = 0; p < PY; p++) {
                            ffma2(acc[p][4 * h + 0], vv[p], a.x);
                            ffma2(acc[p][4 * h + 1], vv[p], a.y);
                            ffma2(acc[p][4 * h + 2], vv[p], c.x);
                            ffma2(acc[p][4 * h + 3], vv[p], c.y);
                        }
                    }
                }
            }
        }
    }

    __syncthreads();   // all s_h reads done; safe to reuse as s_pool

    // ---- gates (i, f, c, o), write c/h, stage h for pooling ----
    #pragma unroll
    for (int p = 0; p < PY; p++) {
        int gy = y0 + ry[p];
        int gx = x0 + lx;
        bool valid = (ry[p] < TY) && (gy < HO) && (gx < WO);
        float hn[FT];
        #pragma unroll
        for (int j = 0; j < FT; j++) hn[j] = -INFINITY;

        if (valid) {
            float va[G4];
            #pragma unroll
            for (int q = 0; q < NQ; q++) {
                unsigned int lo, hi;
                asm("mov.b64 {%0, %1}, %2;" : "=r"(lo), "=r"(hi) : "l"(acc[p][q]));
                va[2 * q]     = __uint_as_float(lo);
                va[2 * q + 1] = __uint_as_float(hi);
            }
            size_t pix = (size_t)b * HO * WO + (size_t)gy * WO + gx;
            float* cp = c_buf + pix * F + f0;
            float* ho = hs + ((size_t)(b * Tv + t)) * HO * WO * F
                           + ((size_t)gy * WO + gx) * F + f0;
            float co[FT];
            if (t > 0) {
                if constexpr (FT == 4) {
                    float4 c4v = *reinterpret_cast<const float4*>(cp);
                    co[0] = c4v.x; co[1] = c4v.y; co[2] = c4v.z; co[3] = c4v.w;
                } else {
                    float2 c2v = *reinterpret_cast<const float2*>(cp);
                    co[0] = c2v.x; co[1] = c2v.y;
                }
            } else {
                #pragma unroll
                for (int j = 0; j < FT; j++) co[j] = 0.0f;
            }
            float cn[FT];
            #pragma unroll
            for (int j = 0; j < FT; j++) {
                float iv = va[j];
                float fv = va[FT + j];
                float cv = va[2 * FT + j];
                float ov = va[3 * FT + j];
                float c2 = hsig(fv) * co[j] + hsig(iv) * tanhf(cv);
                cn[j] = c2;
                hn[j] = hsig(ov) * tanhf(c2);
            }
            if constexpr (FT == 4) {
                *reinterpret_cast<float4*>(cp) = make_float4(cn[0], cn[1], cn[2], cn[3]);
                *reinterpret_cast<float4*>(ho) = make_float4(hn[0], hn[1], hn[2], hn[3]);
            } else {
                *reinterpret_cast<float2*>(cp) = make_float2(cn[0], cn[1]);
                *reinterpret_cast<float2*>(ho) = make_float2(hn[0], hn[1]);
            }
        }
        #pragma unroll
        for (int j = 0; j < FT; j++)
            s_pool[(j * BYP + ry[p]) * TX + lx] = hn[j];   // -INF if invalid
    }
    __syncthreads();

    // ---- fused 2x2 maxpool (SAME) on the staged tile ----
    {
        constexpr int TXH = TX / 2, TYH = (TY + 1) / 2;
        for (int i = tid; i < FT * TYH * TXH; i += NTHR) {
            int f = i % FT; int rr = i / FT;
            int oxc = rr % TXH, oyc = rr / TXH;
            int oy = (y0 >> 1) + oyc, ox = (x0 >> 1) + oxc;
            if (oy < HOp && ox < WOp) {
                int r0 = 2 * oyc, r1 = r0 + 1, q0 = 2 * oxc, q1 = q0 + 1;
                float m = fmaxf(s_pool[(f * BYP + r0) * TX + q0],
                                s_pool[(f * BYP + r0) * TX + q1]);
                if (r1 < TY)
                    m = fmaxf(m, fmaxf(s_pool[(f * BYP + r1) * TX + q0],
                                       s_pool[(f * BYP + r1) * TX + q1]));
                pool_out[(((size_t)(b * Tv + t) * HOp + oy) * WOp + ox) * F + f0 + f] = m;
            }
        }
    }
}

// Block counts per layer (flat grid, L1 first = longest first)
static constexpr int NB1 = 1024;   // 32b * 8yt * 4xt * 1g
static constexpr int NB2 = 512;    // 32b * 4yt * 2xt * 2g
static constexpr int NB3 = 768;    // 32b * 4yt * 1xt * 6g
static constexpr int NB4 = 256;    // 32b * 1  * 1  * 8g
static constexpr int NBT = NB1 + NB2 + NB3 + NB4;   // 2560

// Mega-step: flat grid, block ranges select the layer; skewed timesteps.
__global__ void __launch_bounds__(256, 5) mega_step(
    const float* __restrict__ x,
    const float* __restrict__ Wx1, const float* __restrict__ Wh1, const float* __restrict__ b1,
    const float* __restrict__ Wx2, const float* __restrict__ Wh2, const float* __restrict__ b2,
    const float* __restrict__ Wx3, const float* __restrict__ Wh3, const float* __restrict__ b3,
    const float* __restrict__ Wx4, const float* __restrict__ Wh4, const float* __restrict__ b4,
    float* hs1, float* c1, float* p1,
    float* hs2, float* c2, float* p2,
    float* hs3, float* c3, float* p3,
    float* hs4, float* c4, float* p4,
    int t1, int t2, int t3, int t4)
{
    __shared__ __align__(16) char raw[SMEM_RAW];
    const int bid = blockIdx.x;
    if (bid < NB1) {
        if (t1 >= 0)
            lstm_impl<3, 4, 4, 128, 128, 32, 16>(raw, bid, x, Wx1, Wh1, b1, hs1, c1, p1, t1);
    } else if (bid < NB1 + NB2) {
        if (t2 >= 0)
            lstm_impl<4, 8, 4, 63, 63, 32, 16>(raw, bid - NB1, p1, Wx2, Wh2, b2, hs2, c2, p2, t2);
    } else if (bid < NB1 + NB2 + NB3) {
        if (t3 >= 0)
            lstm_impl<8, 12, 2, 31, 31, 32, 8>(raw, bid - NB1 - NB2, p2, Wx3, Wh3, b3, hs3, c3, p3, t3);
    } else {
        if (t4 >= 0)
            lstm_impl<12, 16, 2, 15, 15, 16, 13>(raw, bid - NB1 - NB2 - NB3, p3, Wx4, Wh4, b4, hs4, c4, p4, t4);
    }
}

// Dense: logits[b,k] = sum_j xf[b,j]*Wd[j,k] + bd[k];   FLAT=18816, NC=50
__global__ void dense_k(const float* __restrict__ xf, const float* __restrict__ Wd,
                        const float* __restrict__ bd, float* __restrict__ logits)
{
    const int FLAT = 18816, NC = 50;
    int b = blockIdx.x, k = blockIdx.y;
    float s = 0.0f;
    for (int j = threadIdx.x; j < FLAT; j += blockDim.x)
        s += xf[(size_t)b * FLAT + j] * __ldg(&Wd[(size_t)j * NC + k]);
    __shared__ float red[128];
    red[threadIdx.x] = s;
    __syncthreads();
    for (int off = 64; off > 0; off >>= 1) {
        if (threadIdx.x < off) red[threadIdx.x] += red[threadIdx.x + off];
        __syncthreads();
    }
    if (threadIdx.x == 0) logits[b * NC + k] = red[0] + __ldg(&bd[k]);
}

__global__ void softmax_k(const float* __restrict__ logits, float* __restrict__ out)
{
    const int NC = 50;
    int b = blockIdx.x, t = threadIdx.x;
    __shared__ float s[64];
    float v = (t < NC) ? logits[b * NC + t] : -INFINITY;
    s[t] = v; __syncthreads();
    for (int off = 32; off > 0; off >>= 1) {
        if (t < off) s[t] = fmaxf(s[t], s[t + off]);
        __syncthreads();
    }
    float m = s[0]; __syncthreads();
    float e = (t < NC) ? expf(v - m) : 0.0f;
    s[t] = e; __syncthreads();
    for (int off = 32; off > 0; off >>= 1) {
        if (t < off) s[t] += s[t + off];
        __syncthreads();
    }
    float sum = s[0];
    if (t < NC) out[b * NC + t] = e / sum;
}

template <typename Sym>
static float* symaddr(const Sym& s) {
    void* p = nullptr;
    cudaGetSymbolAddress(&p, s);
    return (float*)p;
}

extern "C" void kernel_launch(void* const* d_in, const int* in_sizes, int n_in,
                              void* d_out, int out_size)
{
    const float* x   = (const float*)d_in[0];
    const float* Wx1 = (const float*)d_in[1];
    const float* Wh1 = (const float*)d_in[2];
    const float* b1  = (const float*)d_in[3];
    const float* Wx2 = (const float*)d_in[4];
    const float* Wh2 = (const float*)d_in[5];
    const float* b2  = (const float*)d_in[6];
    const float* Wx3 = (const float*)d_in[7];
    const float* Wh3 = (const float*)d_in[8];
    const float* b3  = (const float*)d_in[9];
    const float* Wx4 = (const float*)d_in[10];
    const float* Wh4 = (const float*)d_in[11];
    const float* b4  = (const float*)d_in[12];
    const float* Wd  = (const float*)d_in[13];
    const float* bd  = (const float*)d_in[14];
    float* out = (float*)d_out;

    float* hs1 = symaddr(g_hs1); float* c1 = symaddr(g_c1); float* p1 = symaddr(g_p1);
    float* hs2 = symaddr(g_hs2); float* c2 = symaddr(g_c2); float* p2 = symaddr(g_p2);
    float* hs3 = symaddr(g_hs3); float* c3 = symaddr(g_c3); float* p3 = symaddr(g_p3);
    float* hs4 = symaddr(g_hs4); float* c4 = symaddr(g_c4); float* p4 = symaddr(g_p4);
    float* logits = symaddr(g_logits);

    // Skewed pipeline: launch s runs L1@s, L2@s-1, L3@s-2, L4@s-3.
    dim3 grid(NBT), blk(256);
    for (int s = 0; s < Tv + 3; s++) {
        int t1 = (s < Tv) ? s : -1;
        int t2 = (s - 1 >= 0 && s - 1 < Tv) ? s - 1 : -1;
        int t3 = (s - 2 >= 0 && s - 2 < Tv) ? s - 2 : -1;
        int t4 = (s - 3 >= 0 && s - 3 < Tv) ? s - 3 : -1;
        mega_step<<<grid, blk>>>(x,
                                 Wx1, Wh1, b1, Wx2, Wh2, b2,
                                 Wx3, Wh3, b3, Wx4, Wh4, b4,
                                 hs1, c1, p1, hs2, c2, p2,
                                 hs3, c3, p3, hs4, c4, p4,
                                 t1, t2, t3, t4);
    }

    // ---- Dense + softmax ----
    dim3 dgrid(Bv, 50);
    dense_k<<<dgrid, 128>>>(p4, Wd, bd, logits);
    softmax_k<<<Bv, 64>>>(logits, out);
}

// round 13
// speedup vs baseline: 1.0418x; 1.0220x over previous
#include <cuda_runtime.h>
#include <math.h>

// ---------------------------------------------------------------------------
// ConvLSTM stack, R12: exact R9 kernel (skewed pipeline + FFMA2, best 2517us,
// launch_bounds(256,4)) with ONE change: fast exp2-based tanh in the gate
// epilogue (~8 instr vs ~25 for libdevice tanhf; rel err ~1e-6).
// ---------------------------------------------------------------------------

static constexpr int Bv = 32;
static constexpr int Tv = 24;

__device__ float g_hs1[(size_t)Bv*Tv*126*126*4];
__device__ float g_c1 [(size_t)Bv*126*126*4];
__device__ float g_p1 [(size_t)Bv*Tv*63*63*4];
__device__ float g_hs2[(size_t)Bv*Tv*61*61*8];
__device__ float g_c2 [(size_t)Bv*61*61*8];
__device__ float g_p2 [(size_t)Bv*Tv*31*31*8];
__device__ float g_hs3[(size_t)Bv*Tv*29*29*12];
__device__ float g_c3 [(size_t)Bv*29*29*12];
__device__ float g_p3 [(size_t)Bv*Tv*15*15*12];
__device__ float g_hs4[(size_t)Bv*Tv*13*13*16];
__device__ float g_c4 [(size_t)Bv*13*13*16];
__device__ float g_p4 [(size_t)Bv*Tv*7*7*16];
__device__ float g_logits[Bv*50];

__device__ __forceinline__ float hsig(float x) { return __saturatef(0.2f * x + 0.5f); }

// Fast accurate-enough tanh: (e^{2x}-1)/(e^{2x}+1) via MUFU.EX2 + MUFU.RCP.
// Clamped to |x|<=9 (tanh(9) == 1.0f in fp32). Rel err ~1e-6.
__device__ __forceinline__ float fast_tanh(float x) {
    float xc = fminf(fmaxf(x, -9.0f), 9.0f);
    float t = __expf(2.0f * xc);
    return __fdividef(t - 1.0f, t + 1.0f);
}

__device__ __forceinline__ unsigned long long pack2(float v) {
    unsigned long long r;
    asm("mov.b64 %0, {%1, %1};" : "=l"(r) : "f"(v));
    return r;
}
__device__ __forceinline__ void ffma2(unsigned long long& d, unsigned long long a,
                                      unsigned long long b) {
    asm("fma.rn.f32x2 %0, %1, %2, %0;" : "+l"(d) : "l"(a), "l"(b));
}

static constexpr int SMEM_RAW = 38400;   // >= max per-layer need (38304 B, L4)

// One ConvLSTM timestep for one layer + fused 2x2 maxpool.
// Flat 256-thread block; FT gate channels per block (G4 = 4*FT gate values,
// held as NQ = G4/2 packed f32x2 accumulators).
template<int CIN, int F, int FT, int HIN, int WIN, int TX, int TY>
__device__ __forceinline__ void lstm_impl(
    char* raw, int bid,
    const float* __restrict__ in_seq,   // (B,T,HIN,WIN,CIN)
    const float* __restrict__ Wx,       // (3,3,CIN,4F)
    const float* __restrict__ Wh,       // (3,3,F,4F)
    const float* __restrict__ bias,     // (4F,)
    float* __restrict__ hs,             // (B,T,HO,WO,F)
    float* __restrict__ c_buf,          // (B,HO,WO,F)
    float* __restrict__ pool_out,       // (B,T,HOp,WOp,F)
    int t)
{
    constexpr int NTHR = 256;
    constexpr int BY = NTHR / TX;
    constexpr int PY = (TY + BY - 1) / BY;
    constexpr int BYP = BY * PY;
    constexpr int G4 = 4 * FT;
    constexpr int NQ = G4 / 2;          // packed accumulators (8 or 4)
    constexpr int NH = NQ / 4;          // halves of 4 b64 (2 or 1)
    constexpr int HO = HIN - 2, WO = WIN - 2;
    constexpr int HOp = (HO + 1) / 2, WOp = (WO + 1) / 2;
    constexpr int C4 = 4 * F;
    constexpr int TXP = TX + 2, TYP = TY + 2;
    constexpr int NXT = (WO + TX - 1) / TX;
    constexpr int NYT = (HO + TY - 1) / TY;
    constexpr int NG = F / FT;

    float* s_in = reinterpret_cast<float*>(raw);
    float* s_h  = s_in + CIN * TYP * TXP;
    float* s_wx = s_h  + F * TYP * TXP;
    float* s_wh = s_wx + 9 * CIN * G4;
    float* s_pool = s_h;   // reused after mainloop

    int r = bid;
    const int g  = r % NG;  r /= NG;
    const int xT = r % NXT; r /= NXT;
    const int yT = r % NYT; const int b = r / NYT;
    const int x0 = xT * TX, y0 = yT * TY;     // even (or single tile)
    const int f0 = g * FT;
    const int tid = threadIdx.x;
    const int lx = tid % TX, ly = tid / TX;

    // ---- weights (gate-column slice) into smem: [(tap*C+ci)][g*FT+j] ----
    for (int i = tid; i < 9 * CIN * G4; i += NTHR) {
        int col = i % G4, rc = i / G4;
        s_wx[i] = Wx[rc * C4 + (col / FT) * F + f0 + (col % FT)];
    }
    for (int i = tid; i < 9 * F * G4; i += NTHR) {
        int col = i % G4, rc = i / G4;
        s_wh[i] = Wh[rc * C4 + (col / FT) * F + f0 + (col % FT)];
    }

    // ---- input tile (planar, zero-padded) ----
    {
        const float* xin = in_seq + ((size_t)(b * Tv + t)) * HIN * WIN * CIN;
        for (int i = tid; i < TYP * TXP * CIN; i += NTHR) {
            int ci = i % CIN; int rr = i / CIN;
            int xx = rr % TXP; int yy = rr / TXP;
            int gy = y0 + yy, gx = x0 + xx;
            float v = (gy < HIN && gx < WIN) ? __ldg(&xin[((size_t)gy * WIN + gx) * CIN + ci]) : 0.0f;
            s_in[(ci * TYP + yy) * TXP + xx] = v;
        }
    }
    // ---- h_{t-1} tile (planar, zero-padded) ----
    if (t > 0) {
        const float* hp = hs + ((size_t)(b * Tv + (t - 1))) * HO * WO * F;
        for (int i = tid; i < TYP * TXP * F; i += NTHR) {
            int ci = i % F; int rr = i / F;
            int xx = rr % TXP; int yy = rr / TXP;
            int hr = y0 - 1 + yy, hc = x0 - 1 + xx;
            float v = (hr >= 0 && hr < HO && hc >= 0 && hc < WO)
                        ? __ldg(&hp[((size_t)hr * WO + hc) * F + ci]) : 0.0f;
            s_h[(ci * TYP + yy) * TXP + xx] = v;
        }
    }
    __syncthreads();

    // Row indices per sub-pixel p: ry = logical row, rcl = clamped for smem reads.
    int ry[PY], rcl[PY];
    #pragma unroll
    for (int p = 0; p < PY; p++) {
        ry[p] = ly + p * BY;
        rcl[p] = (ry[p] < TY) ? ry[p] : (TY - 1);
    }

    // Packed accumulators: acc[p][q] = gate values (2q, 2q+1)
    unsigned long long acc[PY][NQ];
    {
        #pragma unroll
        for (int q = 0; q < NQ; q++) {
            int m0 = 2 * q, m1 = 2 * q + 1;
            float b0 = __ldg(&bias[(m0 / FT) * F + f0 + (m0 % FT)]);
            float b1 = __ldg(&bias[(m1 / FT) * F + f0 + (m1 % FT)]);
            unsigned long long bp;
            asm("mov.b64 %0, {%1, %2};" : "=l"(bp) : "f"(b0), "f"(b1));
            #pragma unroll
            for (int p = 0; p < PY; p++) acc[p][q] = bp;
        }
    }

    // ---- input conv (VALID); FFMA2, weight halves of 4 b64 ----
    #pragma unroll
    for (int ky = 0; ky < 3; ky++) {
        #pragma unroll
        for (int kx = 0; kx < 3; kx++) {
            #pragma unroll
            for (int ci = 0; ci < CIN; ci++) {
                unsigned long long vv[PY];
                #pragma unroll
                for (int p = 0; p < PY; p++)
                    vv[p] = pack2(s_in[(ci * TYP + rcl[p] + ky) * TXP + lx + kx]);
                const ulonglong2* wq = reinterpret_cast<const ulonglong2*>(
                    s_wx + ((ky * 3 + kx) * CIN + ci) * G4);
                #pragma unroll
                for (int h = 0; h < NH; h++) {
                    ulonglong2 a = wq[2 * h], c = wq[2 * h + 1];
                    #pragma unroll
                    for (int p = 0; p < PY; p++) {
                        ffma2(acc[p][4 * h + 0], vv[p], a.x);
                        ffma2(acc[p][4 * h + 1], vv[p], a.y);
                        ffma2(acc[p][4 * h + 2], vv[p], c.x);
                        ffma2(acc[p][4 * h + 3], vv[p], c.y);
                    }
                }
            }
        }
    }

    // ---- recurrent conv (SAME) ----
    if (t > 0) {
        #pragma unroll
        for (int ky = 0; ky < 3; ky++) {
            #pragma unroll
            for (int kx = 0; kx < 3; kx++) {
                #pragma unroll
                for (int ci = 0; ci < F; ci++) {
                    unsigned long long vv[PY];
                    #pragma unroll
                    for (int p = 0; p < PY; p++)
                        vv[p] = pack2(s_h[(ci * TYP + rcl[p] + ky) * TXP + lx + kx]);
                    const ulonglong2* wq = reinterpret_cast<const ulonglong2*>(
                        s_wh + ((ky * 3 + kx) * F + ci) * G4);
                    #pragma unroll
                    for (int h = 0; h < NH; h++) {
                        ulonglong2 a = wq[2 * h], c = wq[2 * h + 1];
                        #pragma unroll
                        for (int p = 0; p < PY; p++) {
                            ffma2(acc[p][4 * h + 0], vv[p], a.x);
                            ffma2(acc[p][4 * h + 1], vv[p], a.y);
                            ffma2(acc[p][4 * h + 2], vv[p], c.x);
                            ffma2(acc[p][4 * h + 3], vv[p], c.y);
                        }
                    }
                }
            }
        }
    }

    __syncthreads();   // all s_h reads done; safe to reuse as s_pool

    // ---- gates (i, f, c, o), write c/h, stage h for pooling ----
    #pragma unroll
    for (int p = 0; p < PY; p++) {
        int gy = y0 + ry[p];
        int gx = x0 + lx;
        bool valid = (ry[p] < TY) && (gy < HO) && (gx < WO);
        float hn[FT];
        #pragma unroll
        for (int j = 0; j < FT; j++) hn[j] = -INFINITY;

        if (valid) {
            float va[G4];
            #pragma unroll
            for (int q = 0; q < NQ; q++) {
                unsigned int lo, hi;
                asm("mov.b64 {%0, %1}, %2;" : "=r"(lo), "=r"(hi) : "l"(acc[p][q]));
                va[2 * q]     = __uint_as_float(lo);
                va[2 * q + 1] = __uint_as_float(hi);
            }
            size_t pix = (size_t)b * HO * WO + (size_t)gy * WO + gx;
            float* cp = c_buf + pix * F + f0;
            float* ho = hs + ((size_t)(b * Tv + t)) * HO * WO * F
                           + ((size_t)gy * WO + gx) * F + f0;
            float co[FT];
            if (t > 0) {
                if constexpr (FT == 4) {
                    float4 c4v = *reinterpret_cast<const float4*>(cp);
                    co[0] = c4v.x; co[1] = c4v.y; co[2] = c4v.z; co[3] = c4v.w;
                } else {
                    float2 c2v = *reinterpret_cast<const float2*>(cp);
                    co[0] = c2v.x; co[1] = c2v.y;
                }
            } else {
                #pragma unroll
                for (int j = 0; j < FT; j++) co[j] = 0.0f;
            }
            float cn[FT];
            #pragma unroll
            for (int j = 0; j < FT; j++) {
                float iv = va[j];
                float fv = va[FT + j];
                float cv = va[2 * FT + j];
                float ov = va[3 * FT + j];
                float c2 = hsig(fv) * co[j] + hsig(iv) * fast_tanh(cv);
                cn[j] = c2;
                hn[j] = hsig(ov) * fast_tanh(c2);
            }
            if constexpr (FT == 4) {
                *reinterpret_cast<float4*>(cp) = make_float4(cn[0], cn[1], cn[2], cn[3]);
                *reinterpret_cast<float4*>(ho) = make_float4(hn[0], hn[1], hn[2], hn[3]);
            } else {
                *reinterpret_cast<float2*>(cp) = make_float2(cn[0], cn[1]);
                *reinterpret_cast<float2*>(ho) = make_float2(hn[0], hn[1]);
            }
        }
        #pragma unroll
        for (int j = 0; j < FT; j++)
            s_pool[(j * BYP + ry[p]) * TX + lx] = hn[j];   // -INF if invalid
    }
    __syncthreads();

    // ---- fused 2x2 maxpool (SAME) on the staged tile ----
    {
        constexpr int TXH = TX / 2, TYH = (TY + 1) / 2;
        for (int i = tid; i < FT * TYH * TXH; i += NTHR) {
            int f = i % FT; int rr = i / FT;
            int oxc = rr % TXH, oyc = rr / TXH;
            int oy = (y0 >> 1) + oyc, ox = (x0 >> 1) + oxc;
            if (oy < HOp && ox < WOp) {
                int r0 = 2 * oyc, r1 = r0 + 1, q0 = 2 * oxc, q1 = q0 + 1;
                float m = fmaxf(s_pool[(f * BYP + r0) * TX + q0],
                                s_pool[(f * BYP + r0) * TX + q1]);
                if (r1 < TY)
                    m = fmaxf(m, fmaxf(s_pool[(f * BYP + r1) * TX + q0],
                                       s_pool[(f * BYP + r1) * TX + q1]));
                pool_out[(((size_t)(b * Tv + t) * HOp + oy) * WOp + ox) * F + f0 + f] = m;
            }
        }
    }
}

// Block counts per layer (flat grid, L1 first = longest first)
static constexpr int NB1 = 1024;   // 32b * 8yt * 4xt * 1g
static constexpr int NB2 = 512;    // 32b * 4yt * 2xt * 2g
static constexpr int NB3 = 768;    // 32b * 4yt * 1xt * 6g
static constexpr int NB4 = 256;    // 32b * 1  * 1  * 8g
static constexpr int NBT = NB1 + NB2 + NB3 + NB4;   // 2560

// Mega-step: flat grid, block ranges select the layer; skewed timesteps.
__global__ void __launch_bounds__(256, 4) mega_step(
    const float* __restrict__ x,
    const float* __restrict__ Wx1, const float* __restrict__ Wh1, const float* __restrict__ b1,
    const float* __restrict__ Wx2, const float* __restrict__ Wh2, const float* __restrict__ b2,
    const float* __restrict__ Wx3, const float* __restrict__ Wh3, const float* __restrict__ b3,
    const float* __restrict__ Wx4, const float* __restrict__ Wh4, const float* __restrict__ b4,
    float* hs1, float* c1, float* p1,
    float* hs2, float* c2, float* p2,
    float* hs3, float* c3, float* p3,
    float* hs4, float* c4, float* p4,
    int t1, int t2, int t3, int t4)
{
    __shared__ __align__(16) char raw[SMEM_RAW];
    const int bid = blockIdx.x;
    if (bid < NB1) {
        if (t1 >= 0)
            lstm_impl<3, 4, 4, 128, 128, 32, 16>(raw, bid, x, Wx1, Wh1, b1, hs1, c1, p1, t1);
    } else if (bid < NB1 + NB2) {
        if (t2 >= 0)
            lstm_impl<4, 8, 4, 63, 63, 32, 16>(raw, bid - NB1, p1, Wx2, Wh2, b2, hs2, c2, p2, t2);
    } else if (bid < NB1 + NB2 + NB3) {
        if (t3 >= 0)
            lstm_impl<8, 12, 2, 31, 31, 32, 8>(raw, bid - NB1 - NB2, p2, Wx3, Wh3, b3, hs3, c3, p3, t3);
    } else {
        if (t4 >= 0)
            lstm_impl<12, 16, 2, 15, 15, 16, 13>(raw, bid - NB1 - NB2 - NB3, p3, Wx4, Wh4, b4, hs4, c4, p4, t4);
    }
}

// Dense: logits[b,k] = sum_j xf[b,j]*Wd[j,k] + bd[k];   FLAT=18816, NC=50
__global__ void dense_k(const float* __restrict__ xf, const float* __restrict__ Wd,
                        const float* __restrict__ bd, float* __restrict__ logits)
{
    const int FLAT = 18816, NC = 50;
    int b = blockIdx.x, k = blockIdx.y;
    float s = 0.0f;
    for (int j = threadIdx.x; j < FLAT; j += blockDim.x)
        s += xf[(size_t)b * FLAT + j] * __ldg(&Wd[(size_t)j * NC + k]);
    __shared__ float red[128];
    red[threadIdx.x] = s;
    __syncthreads();
    for (int off = 64; off > 0; off >>= 1) {
        if (threadIdx.x < off) red[threadIdx.x] += red[threadIdx.x + off];
        __syncthreads();
    }
    if (threadIdx.x == 0) logits[b * NC + k] = red[0] + __ldg(&bd[k]);
}

__global__ void softmax_k(const float* __restrict__ logits, float* __restrict__ out)
{
    const int NC = 50;
    int b = blockIdx.x, t = threadIdx.x;
    __shared__ float s[64];
    float v = (t < NC) ? logits[b * NC + t] : -INFINITY;
    s[t] = v; __syncthreads();
    for (int off = 32; off > 0; off >>= 1) {
        if (t < off) s[t] = fmaxf(s[t], s[t + off]);
        __syncthreads();
    }
    float m = s[0]; __syncthreads();
    float e = (t < NC) ? expf(v - m) : 0.0f;
    s[t] = e; __syncthreads();
    for (int off = 32; off > 0; off >>= 1) {
        if (t < off) s[t] += s[t + off];
        __syncthreads();
    }
    float sum = s[0];
    if (t < NC) out[b * NC + t] = e / sum;
}

template <typename Sym>
static float* symaddr(const Sym& s) {
    void* p = nullptr;
    cudaGetSymbolAddress(&p, s);
    return (float*)p;
}

extern "C" void kernel_launch(void* const* d_in, const int* in_sizes, int n_in,
                              void* d_out, int out_size)
{
    const float* x   = (const float*)d_in[0];
    const float* Wx1 = (const float*)d_in[1];
    const float* Wh1 = (const float*)d_in[2];
    const float* b1  = (const float*)d_in[3];
    const float* Wx2 = (const float*)d_in[4];
    const float* Wh2 = (const float*)d_in[5];
    const float* b2  = (const float*)d_in[6];
    const float* Wx3 = (const float*)d_in[7];
    const float* Wh3 = (const float*)d_in[8];
    const float* b3  = (const float*)d_in[9];
    const float* Wx4 = (const float*)d_in[10];
    const float* Wh4 = (const float*)d_in[11];
    const float* b4  = (const float*)d_in[12];
    const float* Wd  = (const float*)d_in[13];
    const float* bd  = (const float*)d_in[14];
    float* out = (float*)d_out;

    float* hs1 = symaddr(g_hs1); float* c1 = symaddr(g_c1); float* p1 = symaddr(g_p1);
    float* hs2 = symaddr(g_hs2); float* c2 = symaddr(g_c2); float* p2 = symaddr(g_p2);
    float* hs3 = symaddr(g_hs3); float* c3 = symaddr(g_c3); float* p3 = symaddr(g_p3);
    float* hs4 = symaddr(g_hs4); float* c4 = symaddr(g_c4); float* p4 = symaddr(g_p4);
    float* logits = symaddr(g_logits);

    // Skewed pipeline: launch s runs L1@s, L2@s-1, L3@s-2, L4@s-3.
    dim3 grid(NBT), blk(256);
    for (int s = 0; s < Tv + 3; s++) {
        int t1 = (s < Tv) ? s : -1;
        int t2 = (s - 1 >= 0 && s - 1 < Tv) ? s - 1 : -1;
        int t3 = (s - 2 >= 0 && s - 2 < Tv) ? s - 2 : -1;
        int t4 = (s - 3 >= 0 && s - 3 < Tv) ? s - 3 : -1;
        mega_step<<<grid, blk>>>(x,
                                 Wx1, Wh1, b1, Wx2, Wh2, b2,
                                 Wx3, Wh3, b3, Wx4, Wh4, b4,
                                 hs1, c1, p1, hs2, c2, p2,
                                 hs3, c3, p3, hs4, c4, p4,
                                 t1, t2, t3, t4);
    }

    // ---- Dense + softmax ----
    dim3 dgrid(Bv, 50);
    dense_k<<<dgrid, 128>>>(p4, Wd, bd, logits);
    softmax_k<<<Bv, 64>>>(logits, out);
}

// round 15
// speedup vs baseline: 1.0480x; 1.0059x over previous
#include <cuda_runtime.h>
#include <math.h>

// ---------------------------------------------------------------------------
// ConvLSTM stack, R13: exact R12 kernel (skewed pipeline + FFMA2 + fast_tanh,
// best 2499us) with ONE change: PDL (programmatic dependent launch) between
// the 27 mega_step nodes. Weight/const prologue runs before
// cudaGridDependencySynchronize(); dependent tile reads after. Falls back to
// plain launches if the attribute is unsupported.
// ---------------------------------------------------------------------------

static constexpr int Bv = 32;
static constexpr int Tv = 24;

__device__ float g_hs1[(size_t)Bv*Tv*126*126*4];
__device__ float g_c1 [(size_t)Bv*126*126*4];
__device__ float g_p1 [(size_t)Bv*Tv*63*63*4];
__device__ float g_hs2[(size_t)Bv*Tv*61*61*8];
__device__ float g_c2 [(size_t)Bv*61*61*8];
__device__ float g_p2 [(size_t)Bv*Tv*31*31*8];
__device__ float g_hs3[(size_t)Bv*Tv*29*29*12];
__device__ float g_c3 [(size_t)Bv*29*29*12];
__device__ float g_p3 [(size_t)Bv*Tv*15*15*12];
__device__ float g_hs4[(size_t)Bv*Tv*13*13*16];
__device__ float g_c4 [(size_t)Bv*13*13*16];
__device__ float g_p4 [(size_t)Bv*Tv*7*7*16];
__device__ float g_logits[Bv*50];

__device__ __forceinline__ float hsig(float x) { return __saturatef(0.2f * x + 0.5f); }

// Fast accurate-enough tanh: (e^{2x}-1)/(e^{2x}+1) via MUFU.EX2 + MUFU.RCP.
__device__ __forceinline__ float fast_tanh(float x) {
    float xc = fminf(fmaxf(x, -9.0f), 9.0f);
    float t = __expf(2.0f * xc);
    return __fdividef(t - 1.0f, t + 1.0f);
}

__device__ __forceinline__ unsigned long long pack2(float v) {
    unsigned long long r;
    asm("mov.b64 %0, {%1, %1};" : "=l"(r) : "f"(v));
    return r;
}
__device__ __forceinline__ void ffma2(unsigned long long& d, unsigned long long a,
                                      unsigned long long b) {
    asm("fma.rn.f32x2 %0, %1, %2, %0;" : "+l"(d) : "l"(a), "l"(b));
}

static constexpr int SMEM_RAW = 38400;   // >= max per-layer need (38304 B, L4)

// One ConvLSTM timestep for one layer + fused 2x2 maxpool.
// IN_DEP: input tensor depends on the previous launch (L2..L4) -> PDL sync
// before loading it. L1's input is the constant x -> sync after input tile.
template<int CIN, int F, int FT, int HIN, int WIN, int TX, int TY, bool IN_DEP>
__device__ __forceinline__ void lstm_impl(
    char* raw, int bid,
    const float* __restrict__ in_seq,   // (B,T,HIN,WIN,CIN)
    const float* __restrict__ Wx,       // (3,3,CIN,4F)
    const float* __restrict__ Wh,       // (3,3,F,4F)
    const float* __restrict__ bias,     // (4F,)
    float* __restrict__ hs,             // (B,T,HO,WO,F)
    float* __restrict__ c_buf,          // (B,HO,WO,F)
    float* __restrict__ pool_out,       // (B,T,HOp,WOp,F)
    int t)
{
    constexpr int NTHR = 256;
    constexpr int BY = NTHR / TX;
    constexpr int PY = (TY + BY - 1) / BY;
    constexpr int BYP = BY * PY;
    constexpr int G4 = 4 * FT;
    constexpr int NQ = G4 / 2;          // packed accumulators (8 or 4)
    constexpr int NH = NQ / 4;          // halves of 4 b64 (2 or 1)
    constexpr int HO = HIN - 2, WO = WIN - 2;
    constexpr int HOp = (HO + 1) / 2, WOp = (WO + 1) / 2;
    constexpr int C4 = 4 * F;
    constexpr int TXP = TX + 2, TYP = TY + 2;
    constexpr int NXT = (WO + TX - 1) / TX;
    constexpr int NYT = (HO + TY - 1) / TY;
    constexpr int NG = F / FT;

    float* s_in = reinterpret_cast<float*>(raw);
    float* s_h  = s_in + CIN * TYP * TXP;
    float* s_wx = s_h  + F * TYP * TXP;
    float* s_wh = s_wx + 9 * CIN * G4;
    float* s_pool = s_h;   // reused after mainloop

    int r = bid;
    const int g  = r % NG;  r /= NG;
    const int xT = r % NXT; r /= NXT;
    const int yT = r % NYT; const int b = r / NYT;
    const int x0 = xT * TX, y0 = yT * TY;     // even (or single tile)
    const int f0 = g * FT;
    const int tid = threadIdx.x;
    const int lx = tid % TX, ly = tid / TX;

    // ---- weights (gate-column slice) into smem: constant inputs, no dep ----
    for (int i = tid; i < 9 * CIN * G4; i += NTHR) {
        int col = i % G4, rc = i / G4;
        s_wx[i] = Wx[rc * C4 + (col / FT) * F + f0 + (col % FT)];
    }
    for (int i = tid; i < 9 * F * G4; i += NTHR) {
        int col = i % G4, rc = i / G4;
        s_wh[i] = Wh[rc * C4 + (col / FT) * F + f0 + (col % FT)];
    }

    // PDL: wait for the previous launch before reading its outputs.
    if (IN_DEP) cudaGridDependencySynchronize();

    // ---- input tile (planar, zero-padded) ----
    {
        const float* xin = in_seq + ((size_t)(b * Tv + t)) * HIN * WIN * CIN;
        for (int i = tid; i < TYP * TXP * CIN; i += NTHR) {
            int ci = i % CIN; int rr = i / CIN;
            int xx = rr % TXP; int yy = rr / TXP;
            int gy = y0 + yy, gx = x0 + xx;
            float v = (gy < HIN && gx < WIN) ? __ldg(&xin[((size_t)gy * WIN + gx) * CIN + ci]) : 0.0f;
            s_in[(ci * TYP + yy) * TXP + xx] = v;
        }
    }

    if (!IN_DEP) cudaGridDependencySynchronize();

    // ---- h_{t-1} tile (planar, zero-padded) ----
    if (t > 0) {
        const float* hp = hs + ((size_t)(b * Tv + (t - 1))) * HO * WO * F;
        for (int i = tid; i < TYP * TXP * F; i += NTHR) {
            int ci = i % F; int rr = i / F;
            int xx = rr % TXP; int yy = rr / TXP;
            int hr = y0 - 1 + yy, hc = x0 - 1 + xx;
            float v = (hr >= 0 && hr < HO && hc >= 0 && hc < WO)
                        ? __ldg(&hp[((size_t)hr * WO + hc) * F + ci]) : 0.0f;
            s_h[(ci * TYP + yy) * TXP + xx] = v;
        }
    }
    __syncthreads();

    // Row indices per sub-pixel p: ry = logical row, rcl = clamped for smem reads.
    int ry[PY], rcl[PY];
    #pragma unroll
    for (int p = 0; p < PY; p++) {
        ry[p] = ly + p * BY;
        rcl[p] = (ry[p] < TY) ? ry[p] : (TY - 1);
    }

    // Packed accumulators: acc[p][q] = gate values (2q, 2q+1)
    unsigned long long acc[PY][NQ];
    {
        #pragma unroll
        for (int q = 0; q < NQ; q++) {
            int m0 = 2 * q, m1 = 2 * q + 1;
            float b0 = __ldg(&bias[(m0 / FT) * F + f0 + (m0 % FT)]);
            float b1 = __ldg(&bias[(m1 / FT) * F + f0 + (m1 % FT)]);
            unsigned long long bp;
            asm("mov.b64 %0, {%1, %2};" : "=l"(bp) : "f"(b0), "f"(b1));
            #pragma unroll
            for (int p = 0; p < PY; p++) acc[p][q] = bp;
        }
    }

    // ---- input conv (VALID); FFMA2, weight halves of 4 b64 ----
    #pragma unroll
    for (int ky = 0; ky < 3; ky++) {
        #pragma unroll
        for (int kx = 0; kx < 3; kx++) {
            #pragma unroll
            for (int ci = 0; ci < CIN; ci++) {
                unsigned long long vv[PY];
                #pragma unroll
                for (int p = 0; p < PY; p++)
                    vv[p] = pack2(s_in[(ci * TYP + rcl[p] + ky) * TXP + lx + kx]);
                const ulonglong2* wq = reinterpret_cast<const ulonglong2*>(
                    s_wx + ((ky * 3 + kx) * CIN + ci) * G4);
                #pragma unroll
                for (int h = 0; h < NH; h++) {
                    ulonglong2 a = wq[2 * h], c = wq[2 * h + 1];
                    #pragma unroll
                    for (int p = 0; p < PY; p++) {
                        ffma2(acc[p][4 * h + 0], vv[p], a.x);
                        ffma2(acc[p][4 * h + 1], vv[p], a.y);
                        ffma2(acc[p][4 * h + 2], vv[p], c.x);
                        ffma2(acc[p][4 * h + 3], vv[p], c.y);
                    }
                }
            }
        }
    }

    // ---- recurrent conv (SAME) ----
    if (t > 0) {
        #pragma unroll
        for (int ky = 0; ky < 3; ky++) {
            #pragma unroll
            for (int kx = 0; kx < 3; kx++) {
                #pragma unroll
                for (int ci = 0; ci < F; ci++) {
                    unsigned long long vv[PY];
                    #pragma unroll
                    for (int p = 0; p < PY; p++)
                        vv[p] = pack2(s_h[(ci * TYP + rcl[p] + ky) * TXP + lx + kx]);
                    const ulonglong2* wq = reinterpret_cast<const ulonglong2*>(
                        s_wh + ((ky * 3 + kx) * F + ci) * G4);
                    #pragma unroll
                    for (int h = 0; h < NH; h++) {
                        ulonglong2 a = wq[2 * h], c = wq[2 * h + 1];
                        #pragma unroll
                        for (int p = 0; p < PY; p++) {
                            ffma2(acc[p][4 * h + 0], vv[p], a.x);
                            ffma2(acc[p][4 * h + 1], vv[p], a.y);
                            ffma2(acc[p][4 * h + 2], vv[p], c.x);
                            ffma2(acc[p][4 * h + 3], vv[p], c.y);
                        }
                    }
                }
            }
        }
    }

    __syncthreads();   // all s_h reads done; safe to reuse as s_pool

    // ---- gates (i, f, c, o), write c/h, stage h for pooling ----
    #pragma unroll
    for (int p = 0; p < PY; p++) {
        int gy = y0 + ry[p];
        int gx = x0 + lx;
        bool valid = (ry[p] < TY) && (gy < HO) && (gx < WO);
        float hn[FT];
        #pragma unroll
        for (int j = 0; j < FT; j++) hn[j] = -INFINITY;

        if (valid) {
            float va[G4];
            #pragma unroll
            for (int q = 0; q < NQ; q++) {
                unsigned int lo, hi;
                asm("mov.b64 {%0, %1}, %2;" : "=r"(lo), "=r"(hi) : "l"(acc[p][q]));
                va[2 * q]     = __uint_as_float(lo);
                va[2 * q + 1] = __uint_as_float(hi);
            }
            size_t pix = (size_t)b * HO * WO + (size_t)gy * WO + gx;
            float* cp = c_buf + pix * F + f0;
            float* ho = hs + ((size_t)(b * Tv + t)) * HO * WO * F
                           + ((size_t)gy * WO + gx) * F + f0;
            float co[FT];
            if (t > 0) {
                if constexpr (FT == 4) {
                    float4 c4v = *reinterpret_cast<const float4*>(cp);
                    co[0] = c4v.x; co[1] = c4v.y; co[2] = c4v.z; co[3] = c4v.w;
                } else {
                    float2 c2v = *reinterpret_cast<const float2*>(cp);
                    co[0] = c2v.x; co[1] = c2v.y;
                }
            } else {
                #pragma unroll
                for (int j = 0; j < FT; j++) co[j] = 0.0f;
            }
            float cn[FT];
            #pragma unroll
            for (int j = 0; j < FT; j++) {
                float iv = va[j];
                float fv = va[FT + j];
                float cv = va[2 * FT + j];
                float ov = va[3 * FT + j];
                float c2 = hsig(fv) * co[j] + hsig(iv) * fast_tanh(cv);
                cn[j] = c2;
                hn[j] = hsig(ov) * fast_tanh(c2);
            }
            if constexpr (FT == 4) {
                *reinterpret_cast<float4*>(cp) = make_float4(cn[0], cn[1], cn[2], cn[3]);
                *reinterpret_cast<float4*>(ho) = make_float4(hn[0], hn[1], hn[2], hn[3]);
            } else {
                *reinterpret_cast<float2*>(cp) = make_float2(cn[0], cn[1]);
                *reinterpret_cast<float2*>(ho) = make_float2(hn[0], hn[1]);
            }
        }
        #pragma unroll
        for (int j = 0; j < FT; j++)
            s_pool[(j * BYP + ry[p]) * TX + lx] = hn[j];   // -INF if invalid
    }
    __syncthreads();

    // ---- fused 2x2 maxpool (SAME) on the staged tile ----
    {
        constexpr int TXH = TX / 2, TYH = (TY + 1) / 2;
        for (int i = tid; i < FT * TYH * TXH; i += NTHR) {
            int f = i % FT; int rr = i / FT;
            int oxc = rr % TXH, oyc = rr / TXH;
            int oy = (y0 >> 1) + oyc, ox = (x0 >> 1) + oxc;
            if (oy < HOp && ox < WOp) {
                int r0 = 2 * oyc, r1 = r0 + 1, q0 = 2 * oxc, q1 = q0 + 1;
                float m = fmaxf(s_pool[(f * BYP + r0) * TX + q0],
                                s_pool[(f * BYP + r0) * TX + q1]);
                if (r1 < TY)
                    m = fmaxf(m, fmaxf(s_pool[(f * BYP + r1) * TX + q0],
                                       s_pool[(f * BYP + r1) * TX + q1]));
                pool_out[(((size_t)(b * Tv + t) * HOp + oy) * WOp + ox) * F + f0 + f] = m;
            }
        }
    }
}

// Block counts per layer (flat grid, L1 first = longest first)
static constexpr int NB1 = 1024;   // 32b * 8yt * 4xt * 1g
static constexpr int NB2 = 512;    // 32b * 4yt * 2xt * 2g
static constexpr int NB3 = 768;    // 32b * 4yt * 1xt * 6g
static constexpr int NB4 = 256;    // 32b * 1  * 1  * 8g
static constexpr int NBT = NB1 + NB2 + NB3 + NB4;   // 2560

// Mega-step: flat grid, block ranges select the layer; skewed timesteps.
__global__ void __launch_bounds__(256, 4) mega_step(
    const float* __restrict__ x,
    const float* __restrict__ Wx1, const float* __restrict__ Wh1, const float* __restrict__ b1,
    const float* __restrict__ Wx2, const float* __restrict__ Wh2, const float* __restrict__ b2,
    const float* __restrict__ Wx3, const float* __restrict__ Wh3, const float* __restrict__ b3,
    const float* __restrict__ Wx4, const float* __restrict__ Wh4, const float* __restrict__ b4,
    float* hs1, float* c1, float* p1,
    float* hs2, float* c2, float* p2,
    float* hs3, float* c3, float* p3,
    float* hs4, float* c4, float* p4,
    int t1, int t2, int t3, int t4)
{
    __shared__ __align__(16) char raw[SMEM_RAW];
    const int bid = blockIdx.x;
    if (bid < NB1) {
        if (t1 >= 0)
            lstm_impl<3, 4, 4, 128, 128, 32, 16, false>(raw, bid, x, Wx1, Wh1, b1, hs1, c1, p1, t1);
    } else if (bid < NB1 + NB2) {
        if (t2 >= 0)
            lstm_impl<4, 8, 4, 63, 63, 32, 16, true>(raw, bid - NB1, p1, Wx2, Wh2, b2, hs2, c2, p2, t2);
    } else if (bid < NB1 + NB2 + NB3) {
        if (t3 >= 0)
            lstm_impl<8, 12, 2, 31, 31, 32, 8, true>(raw, bid - NB1 - NB2, p2, Wx3, Wh3, b3, hs3, c3, p3, t3);
    } else {
        if (t4 >= 0)
            lstm_impl<12, 16, 2, 15, 15, 16, 13, true>(raw, bid - NB1 - NB2 - NB3, p3, Wx4, Wh4, b4, hs4, c4, p4, t4);
    }
}

// Dense: logits[b,k] = sum_j xf[b,j]*Wd[j,k] + bd[k];   FLAT=18816, NC=50
__global__ void dense_k(const float* __restrict__ xf, const float* __restrict__ Wd,
                        const float* __restrict__ bd, float* __restrict__ logits)
{
    const int FLAT = 18816, NC = 50;
    int b = blockIdx.x, k = blockIdx.y;
    float s = 0.0f;
    for (int j = threadIdx.x; j < FLAT; j += blockDim.x)
        s += xf[(size_t)b * FLAT + j] * __ldg(&Wd[(size_t)j * NC + k]);
    __shared__ float red[128];
    red[threadIdx.x] = s;
    __syncthreads();
    for (int off = 64; off > 0; off >>= 1) {
        if (threadIdx.x < off) red[threadIdx.x] += red[threadIdx.x + off];
        __syncthreads();
    }
    if (threadIdx.x == 0) logits[b * NC + k] = red[0] + __ldg(&bd[k]);
}

__global__ void softmax_k(const float* __restrict__ logits, float* __restrict__ out)
{
    const int NC = 50;
    int b = blockIdx.x, t = threadIdx.x;
    __shared__ float s[64];
    float v = (t < NC) ? logits[b * NC + t] : -INFINITY;
    s[t] = v; __syncthreads();
    for (int off = 32; off > 0; off >>= 1) {
        if (t < off) s[t] = fmaxf(s[t], s[t + off]);
        __syncthreads();
    }
    float m = s[0]; __syncthreads();
    float e = (t < NC) ? expf(v - m) : 0.0f;
    s[t] = e; __syncthreads();
    for (int off = 32; off > 0; off >>= 1) {
        if (t < off) s[t] += s[t + off];
        __syncthreads();
    }
    float sum = s[0];
    if (t < NC) out[b * NC + t] = e / sum;
}

template <typename Sym>
static float* symaddr(const Sym& s) {
    void* p = nullptr;
    cudaGetSymbolAddress(&p, s);
    return (float*)p;
}

extern "C" void kernel_launch(void* const* d_in, const int* in_sizes, int n_in,
                              void* d_out, int out_size)
{
    const float* x   = (const float*)d_in[0];
    const float* Wx1 = (const float*)d_in[1];
    const float* Wh1 = (const float*)d_in[2];
    const float* b1  = (const float*)d_in[3];
    const float* Wx2 = (const float*)d_in[4];
    const float* Wh2 = (const float*)d_in[5];
    const float* b2  = (const float*)d_in[6];
    const float* Wx3 = (const float*)d_in[7];
    const float* Wh3 = (const float*)d_in[8];
    const float* b3  = (const float*)d_in[9];
    const float* Wx4 = (const float*)d_in[10];
    const float* Wh4 = (const float*)d_in[11];
    const float* b4  = (const float*)d_in[12];
    const float* Wd  = (const float*)d_in[13];
    const float* bd  = (const float*)d_in[14];
    float* out = (float*)d_out;

    float* hs1 = symaddr(g_hs1); float* c1 = symaddr(g_c1); float* p1 = symaddr(g_p1);
    float* hs2 = symaddr(g_hs2); float* c2 = symaddr(g_c2); float* p2 = symaddr(g_p2);
    float* hs3 = symaddr(g_hs3); float* c3 = symaddr(g_c3); float* p3 = symaddr(g_p3);
    float* hs4 = symaddr(g_hs4); float* c4 = symaddr(g_c4); float* p4 = symaddr(g_p4);
    float* logits = symaddr(g_logits);

    // Skewed pipeline: launch s runs L1@s, L2@s-1, L3@s-2, L4@s-3.
    // PDL between consecutive mega_steps; plain-launch fallback on error.
    for (int s = 0; s < Tv + 3; s++) {
        int t1 = (s < Tv) ? s : -1;
        int t2 = (s - 1 >= 0 && s - 1 < Tv) ? s - 1 : -1;
        int t3 = (s - 2 >= 0 && s - 2 < Tv) ? s - 2 : -1;
        int t4 = (s - 3 >= 0 && s - 3 < Tv) ? s - 3 : -1;

        cudaLaunchConfig_t cfg = {};
        cfg.gridDim = dim3(NBT);
        cfg.blockDim = dim3(256);
        cfg.dynamicSmemBytes = 0;
        cfg.stream = 0;
        cudaLaunchAttribute attr[1];
        attr[0].id = cudaLaunchAttributeProgrammaticStreamSerialization;
        attr[0].val.programmaticStreamSerializationAllowed = 1;
        cfg.attrs = attr;
        cfg.numAttrs = 1;

        cudaError_t e = cudaLaunchKernelEx(&cfg, mega_step, x,
                                           Wx1, Wh1, b1, Wx2, Wh2, b2,
                                           Wx3, Wh3, b3, Wx4, Wh4, b4,
                                           hs1, c1, p1, hs2, c2, p2,
                                           hs3, c3, p3, hs4, c4, p4,
                                           t1, t2, t3, t4);
        if (e != cudaSuccess) {
            cudaGetLastError();   // clear sticky error
            mega_step<<<NBT, 256>>>(x,
                                    Wx1, Wh1, b1, Wx2, Wh2, b2,
                                    Wx3, Wh3, b3, Wx4, Wh4, b4,
                                    hs1, c1, p1, hs2, c2, p2,
                                    hs3, c3, p3, hs4, c4, p4,
                                    t1, t2, t3, t4);
        }
    }

    // ---- Dense + softmax (plain launches: full serialization) ----
    dim3 dgrid(Bv, 50);
    dense_k<<<dgrid, 128>>>(p4, Wd, bd, logits);
    softmax_k<<<Bv, 64>>>(logits, out);
}